// round 6
// baseline (speedup 1.0000x reference)
#include <cuda_runtime.h>
#include <cuda_bf16.h>

// Problem constants (match reference_code)
#define B_DIM 4
#define L_DIM 4096
#define D_DIM 1024
#define NUM_KEEP 1024
#define NUM_DROP (L_DIM - NUM_KEEP)

// Output layout (flattened tuple, all float32):
//   [0)            outputs_dropped : B * NUM_KEEP * D   = 4,194,304
//   [OFF_MASKED)   outputs_masked  : B * L * D          = 16,777,216
//   [OFF_MASKDROP) mask_drop       : L                  = 4,096
//   [OFF_IDX)      idx_keep echo   : NUM_KEEP           = 1,024
#define OFF_MASKED   (B_DIM * NUM_KEEP * D_DIM)
#define OFF_MASKDROP (OFF_MASKED + B_DIM * L_DIM * D_DIM)
#define OFF_IDX      (OFF_MASKDROP + L_DIM)

// Grid layout: one row (1024 floats = 256 float4) per 256-thread block.
#define MASKED_BLOCKS  (B_DIM * L_DIM)               // 16384
#define DROPPED_BLOCKS (B_DIM * NUM_KEEP)            // 4096
#define TAIL_BLOCKS    16
#define TOTAL_BLOCKS   (MASKED_BLOCKS + DROPPED_BLOCKS + TAIL_BLOCKS)

// lower_bound over sorted idx_keep in GLOBAL memory (uniform across warp ->
// broadcast loads, L1-resident after warmup). 11 iterations to converge n=1024.
__device__ __forceinline__ int lower_bound_g(const int* __restrict__ idx, int v) {
    int lo = 0, hi = NUM_KEEP;
    #pragma unroll
    for (int it = 0; it < 11; ++it) {
        if (lo < hi) {
            int mid = (lo + hi) >> 1;
            if (__ldg(&idx[mid]) < v) lo = mid + 1; else hi = mid;
        }
    }
    return lo;
}

__global__ void __launch_bounds__(256)
mask_stream_kernel(const float4* __restrict__ inputs,
                   const float4* __restrict__ mask_embedding,
                   const int*   __restrict__ idx_keep,
                   float* __restrict__ out) {
    const int tid = threadIdx.x;   // 0..255
    const int bid = blockIdx.x;

    float4* __restrict__ dropped = (float4*)(out);               // [B,K,D]
    float4* __restrict__ masked  = (float4*)(out + OFF_MASKED);  // [B,L,D]

    if (bid < MASKED_BLOCKS) {
        // ---- masked row: membership only (no rank needed)
        const int row = bid;
        const int l   = row & (L_DIM - 1);
        int pos = lower_bound_g(idx_keep, l);
        const bool kept = (pos < NUM_KEEP && __ldg(&idx_keep[pos]) == l);

        const size_t o = (size_t)row * (D_DIM / 4) + tid;
        if (kept) {
            masked[o] = __ldcs(&inputs[o]);
        } else {
            masked[o] = __ldg(&mask_embedding[tid]);
        }
    } else if (bid < MASKED_BLOCKS + DROPPED_BLOCKS) {
        // ---- dropped row: rank is the block index — just gather
        const int k  = bid - MASKED_BLOCKS;      // 0..4095
        const int b  = k >> 10;                  // k / NUM_KEEP
        const int kl = k & (NUM_KEEP - 1);       // k % NUM_KEEP
        const int src_l = __ldg(&idx_keep[kl]);
        const size_t src = ((size_t)b * L_DIM + src_l) * (D_DIM / 4) + tid;
        dropped[(size_t)k * (D_DIM / 4) + tid] = __ldg(&inputs[src]);
    } else {
        // ---- tail: mask_drop (4096 over 16 blocks) + idx echo (first 4)
        const int tb = bid - MASKED_BLOCKS - DROPPED_BLOCKS;  // 0..15
        const int i  = tb * 256 + tid;                        // 0..4095
        int pos = lower_bound_g(idx_keep, i);
        const bool kept = (pos < NUM_KEEP && __ldg(&idx_keep[pos]) == i);
        out[OFF_MASKDROP + i] = kept ? 0.0f : 1.0f;
        if (tb < 4) {
            const int j = tb * 256 + tid;                     // 0..1023
            out[OFF_IDX + j] = (float)__ldg(&idx_keep[j]);
        }
    }
}

// ---------------------------------------------------------------------------
extern "C" void kernel_launch(void* const* d_in, const int* in_sizes, int n_in,
                              void* d_out, int out_size) {
    const float4* inputs         = (const float4*)d_in[0];  // [B, L, D] f32
    const float4* mask_embedding = (const float4*)d_in[1];  // [D] f32
    const int*    idx_keep       = (const int*)d_in[2];     // [NUM_KEEP] i32
    float*        out            = (float*)d_out;

    mask_stream_kernel<<<TOTAL_BLOCKS, 256>>>(inputs, mask_embedding, idx_keep, out);
}

// round 9
// speedup vs baseline: 1.6750x; 1.6750x over previous
#include <cuda_runtime.h>
#include <cuda_bf16.h>

// Problem constants (match reference_code)
#define B_DIM 4
#define L_DIM 4096
#define D_DIM 1024
#define NUM_KEEP 1024
#define NUM_DROP (L_DIM - NUM_KEEP)

// Output layout (flattened tuple, all float32):
//   [0)            outputs_dropped : B * NUM_KEEP * D   = 4,194,304
//   [OFF_MASKED)   outputs_masked  : B * L * D          = 16,777,216
//   [OFF_MASKDROP) mask_drop       : L                  = 4,096
//   [OFF_IDX)      idx_keep echo   : NUM_KEEP           = 1,024
#define OFF_MASKED   (B_DIM * NUM_KEEP * D_DIM)
#define OFF_MASKDROP (OFF_MASKED + B_DIM * L_DIM * D_DIM)
#define OFF_IDX      (OFF_MASKDROP + L_DIM)

#define ROWS_PER_BLOCK 8
#define MAIN_BLOCKS   ((B_DIM * L_DIM) / ROWS_PER_BLOCK)   // 2048
#define TAIL_BLOCKS   16
#define TOTAL_BLOCKS  (MAIN_BLOCKS + TAIL_BLOCKS)

// 32-byte register bundle as four b64 lanes (256-bit ld/st forms).
struct Chunk256 { unsigned long long x0, x1, x2, x3; };

// ---- L2 eviction-priority memory ops (256-bit, the only legal forms) ------
// Input is single-use per iteration -> evict_first. Output (84 MB) fits in
// L2 (126 MB) -> evict_last keeps it resident across graph replays.
__device__ __forceinline__ Chunk256 ldg256_evict_first(const void* p) {
    Chunk256 c;
    asm volatile("ld.global.L2::evict_first.v4.b64 {%0,%1,%2,%3}, [%4];"
                 : "=l"(c.x0), "=l"(c.x1), "=l"(c.x2), "=l"(c.x3) : "l"(p));
    return c;
}
__device__ __forceinline__ void stg256_evict_last(void* p, Chunk256 c) {
    asm volatile("st.global.L2::evict_last.v4.b64 [%0], {%1,%2,%3,%4};"
                 :: "l"(p), "l"(c.x0), "l"(c.x1), "l"(c.x2), "l"(c.x3) : "memory");
}

// lower_bound over 1024 sorted ints in shared memory (11 iters to converge).
__device__ __forceinline__ int lower_bound_1024(const int* __restrict__ s_idx, int v) {
    int lo = 0, hi = NUM_KEEP;
    #pragma unroll
    for (int it = 0; it < 11; ++it) {
        if (lo < hi) {
            int mid = (lo + hi) >> 1;
            if (s_idx[mid] < v) lo = mid + 1; else hi = mid;
        }
    }
    return lo;
}

__global__ void __launch_bounds__(256)
mask_fused_kernel(const float* __restrict__ inputs,
                  const float* __restrict__ mask_embedding,
                  const int4* __restrict__ idx_keep,
                  float* __restrict__ out) {
    __shared__ int s_idx[NUM_KEEP];
    __shared__ int s_flag[ROWS_PER_BLOCK];

    const int tid = threadIdx.x;   // 0..255
    const int bid = blockIdx.x;

    // Load sorted idx_keep into shared (4 KB; one int4 per thread).
    {
        int4 q = __ldg(&idx_keep[tid]);
        ((int4*)s_idx)[tid] = q;
    }
    __syncthreads();

    if (bid < MAIN_BLOCKS) {
        // ----- main path: 8 rows/block; 2 rows per 256-thread slab pass,
        //       each thread owns one 32-byte chunk of its row.
        const int row0 = bid * ROWS_PER_BLOCK;
        const int r2   = tid >> 7;     // 0..1  : row within slab
        const int c    = tid & 127;    // 0..127: chunk within row (32B each)

        if (tid < ROWS_PER_BLOCK) {
            const int l = (row0 + tid) & (L_DIM - 1);
            int pos = lower_bound_1024(s_idx, l);
            s_flag[tid] = (pos < NUM_KEEP && s_idx[pos] == l) ? (pos + 1) : 0;
        }
        __syncthreads();

        float* __restrict__ dropped = out;               // [B,K,D]
        float* __restrict__ masked  = out + OFF_MASKED;  // [B,L,D]

        // register-cached mask_embedding chunk (8 floats)
        Chunk256 me;
        {
            const unsigned long long* mep =
                (const unsigned long long*)(mask_embedding + c * 8);
            me.x0 = __ldg(&mep[0]); me.x1 = __ldg(&mep[1]);
            me.x2 = __ldg(&mep[2]); me.x3 = __ldg(&mep[3]);
        }

        int flags[4];
        #pragma unroll
        for (int p = 0; p < 4; ++p) flags[p] = s_flag[p * 2 + r2];

        // front-batch keep-row loads (up to 4 independent 256-bit loads)
        Chunk256 v[4];
        #pragma unroll
        for (int p = 0; p < 4; ++p) {
            if (flags[p]) {
                const int row = row0 + p * 2 + r2;
                v[p] = ldg256_evict_first(inputs + (size_t)row * D_DIM + c * 8);
            }
        }

        #pragma unroll
        for (int p = 0; p < 4; ++p) {
            const int row = row0 + p * 2 + r2;
            float* mrow = masked + (size_t)row * D_DIM + c * 8;
            if (flags[p]) {
                const int b = row >> 12;           // row / L_DIM
                const int k = flags[p] - 1;
                stg256_evict_last(mrow, v[p]);
                stg256_evict_last(dropped + ((size_t)b * NUM_KEEP + k) * D_DIM + c * 8, v[p]);
            } else {
                stg256_evict_last(mrow, me);
            }
        }
    } else {
        // ----- tail path: mask_drop (4096 vals over 16 blocks) + idx echo
        const int tb = bid - MAIN_BLOCKS;          // 0..15
        const int i  = tb * 256 + tid;             // 0..4095
        int pos = lower_bound_1024(s_idx, i);
        bool kept = (pos < NUM_KEEP && s_idx[pos] == i);
        out[OFF_MASKDROP + i] = kept ? 0.0f : 1.0f;
        if (tb < 4) {
            const int j = tb * 256 + tid;          // 0..1023
            out[OFF_IDX + j] = (float)s_idx[j];
        }
    }
}

// ---------------------------------------------------------------------------
extern "C" void kernel_launch(void* const* d_in, const int* in_sizes, int n_in,
                              void* d_out, int out_size) {
    const float* inputs         = (const float*)d_in[0];  // [B, L, D] f32
    const float* mask_embedding = (const float*)d_in[1];  // [D] f32
    const int4*  idx_keep       = (const int4*)d_in[2];   // [NUM_KEEP] i32
    float*       out            = (float*)d_out;

    mask_fused_kernel<<<TOTAL_BLOCKS, 256>>>(inputs, mask_embedding, idx_keep, out);
}

// round 10
// speedup vs baseline: 1.6778x; 1.0017x over previous
#include <cuda_runtime.h>
#include <cuda_bf16.h>

// Problem constants (match reference_code)
#define B_DIM 4
#define L_DIM 4096
#define D_DIM 1024
#define NUM_KEEP 1024
#define NUM_DROP (L_DIM - NUM_KEEP)

// Output layout (flattened tuple, all float32):
//   [0)            outputs_dropped : B * NUM_KEEP * D   = 4,194,304
//   [OFF_MASKED)   outputs_masked  : B * L * D          = 16,777,216
//   [OFF_MASKDROP) mask_drop       : L                  = 4,096
//   [OFF_IDX)      idx_keep echo   : NUM_KEEP           = 1,024
#define OFF_MASKED   (B_DIM * NUM_KEEP * D_DIM)
#define OFF_MASKDROP (OFF_MASKED + B_DIM * L_DIM * D_DIM)
#define OFF_IDX      (OFF_MASKDROP + L_DIM)

#define ROWS_PER_BLOCK 8
#define MAIN_BLOCKS   ((B_DIM * L_DIM) / ROWS_PER_BLOCK)   // 2048
#define TAIL_BLOCKS   16
#define TOTAL_BLOCKS  (MAIN_BLOCKS + TAIL_BLOCKS)

// lower_bound over sorted idx_keep in GLOBAL memory (tail blocks only; the
// 16 tail blocks are fully hidden behind 2048 streaming blocks).
__device__ __forceinline__ int lower_bound_g(const int* __restrict__ idx, int v) {
    int lo = 0, hi = NUM_KEEP;
    #pragma unroll
    for (int it = 0; it < 11; ++it) {
        if (lo < hi) {
            int mid = (lo + hi) >> 1;
            if (__ldg(&idx[mid]) < v) lo = mid + 1; else hi = mid;
        }
    }
    return lo;
}

__global__ void __launch_bounds__(256)
mask_fused_kernel(const float4* __restrict__ inputs,
                  const float4* __restrict__ mask_embedding,
                  const int4*  __restrict__ idx_keep,
                  float* __restrict__ out) {
    // Tiny flag array only — no 4 KB index copy, no LDS binary search.
    __shared__ int s_flag[ROWS_PER_BLOCK];

    const int tid = threadIdx.x;   // 0..255
    const int bid = blockIdx.x;

    if (bid < MAIN_BLOCKS) {
        // ----- main path: 8 consecutive (b,l) rows, one float4 column/thread
        const int row0 = bid * ROWS_PER_BLOCK;
        const int l0   = row0 & (L_DIM - 1);   // 8 rows never straddle a batch

        // zero the 8 flags
        if (tid < ROWS_PER_BLOCK) s_flag[tid] = 0;

        // Each thread tests its 4 idx values (rank = 4*tid+j) against the
        // window [l0, l0+8). Values are unique -> conflict-free scatter.
        const int4 q = __ldg(&idx_keep[tid]);
        __syncthreads();
        {
            unsigned d;
            d = (unsigned)(q.x - l0); if (d < ROWS_PER_BLOCK) s_flag[d] = 4 * tid + 1;
            d = (unsigned)(q.y - l0); if (d < ROWS_PER_BLOCK) s_flag[d] = 4 * tid + 2;
            d = (unsigned)(q.z - l0); if (d < ROWS_PER_BLOCK) s_flag[d] = 4 * tid + 3;
            d = (unsigned)(q.w - l0); if (d < ROWS_PER_BLOCK) s_flag[d] = 4 * tid + 4;
        }
        __syncthreads();

        float4* __restrict__ dropped = (float4*)(out);               // [B,K,D]
        float4* __restrict__ masked  = (float4*)(out + OFF_MASKED);  // [B,L,D]
        const float4 me = __ldg(&mask_embedding[tid]);

        int flags[ROWS_PER_BLOCK];
        #pragma unroll
        for (int r = 0; r < ROWS_PER_BLOCK; ++r) flags[r] = s_flag[r];

        // front-batch keep-row loads for MLP
        float4 v[ROWS_PER_BLOCK];
        #pragma unroll
        for (int r = 0; r < ROWS_PER_BLOCK; ++r) {
            if (flags[r]) {
                v[r] = __ldg(&inputs[(size_t)(row0 + r) * (D_DIM / 4) + tid]);
            }
        }

        #pragma unroll
        for (int r = 0; r < ROWS_PER_BLOCK; ++r) {
            const int    row    = row0 + r;
            const size_t row_f4 = (size_t)row * (D_DIM / 4);
            if (flags[r]) {
                const int b = row >> 12;           // row / L_DIM
                const int k = flags[r] - 1;
                masked[row_f4 + tid] = v[r];
                dropped[((size_t)b * NUM_KEEP + k) * (D_DIM / 4) + tid] = v[r];
            } else {
                masked[row_f4 + tid] = me;
            }
        }
    } else {
        // ----- tail path: mask_drop (4096 over 16 blocks) + idx echo
        const int* idx32 = (const int*)idx_keep;
        const int tb = bid - MAIN_BLOCKS;          // 0..15
        const int i  = tb * 256 + tid;             // 0..4095
        int pos = lower_bound_g(idx32, i);
        bool kept = (pos < NUM_KEEP && __ldg(&idx32[pos]) == i);
        out[OFF_MASKDROP + i] = kept ? 0.0f : 1.0f;
        if (tb < 4) {
            const int j = tb * 256 + tid;          // 0..1023
            out[OFF_IDX + j] = (float)__ldg(&idx32[j]);
        }
    }
}

// ---------------------------------------------------------------------------
extern "C" void kernel_launch(void* const* d_in, const int* in_sizes, int n_in,
                              void* d_out, int out_size) {
    const float4* inputs         = (const float4*)d_in[0];  // [B, L, D] f32
    const float4* mask_embedding = (const float4*)d_in[1];  // [D] f32
    const int4*   idx_keep       = (const int4*)d_in[2];    // [NUM_KEEP] i32
    float*        out            = (float*)d_out;

    mask_fused_kernel<<<TOTAL_BLOCKS, 256>>>(inputs, mask_embedding, idx_keep, out);
}

// round 11
// speedup vs baseline: 1.9070x; 1.1366x over previous
#include <cuda_runtime.h>
#include <cuda_bf16.h>

// Problem constants (match reference_code)
#define B_DIM 4
#define L_DIM 4096
#define D_DIM 1024
#define NUM_KEEP 1024
#define NUM_DROP (L_DIM - NUM_KEEP)

// Output layout (flattened tuple, all float32):
//   [0)            outputs_dropped : B * NUM_KEEP * D   = 4,194,304
//   [OFF_MASKED)   outputs_masked  : B * L * D          = 16,777,216
//   [OFF_MASKDROP) mask_drop       : L                  = 4,096
//   [OFF_IDX)      idx_keep echo   : NUM_KEEP           = 1,024
#define OFF_MASKED   (B_DIM * NUM_KEEP * D_DIM)
#define OFF_MASKDROP (OFF_MASKED + B_DIM * L_DIM * D_DIM)
#define OFF_IDX      (OFF_MASKDROP + L_DIM)

#define ROWS_PER_BLOCK 8
#define MAIN_BLOCKS   ((B_DIM * L_DIM) / ROWS_PER_BLOCK)   // 2048
#define TAIL_BLOCKS   16
#define TOTAL_BLOCKS  (MAIN_BLOCKS + TAIL_BLOCKS)

// lower_bound over sorted idx_keep in GLOBAL memory (tail blocks only; the
// 16 tail blocks are fully hidden behind 2048 streaming blocks).
__device__ __forceinline__ int lower_bound_g(const int* __restrict__ idx, int v) {
    int lo = 0, hi = NUM_KEEP;
    #pragma unroll
    for (int it = 0; it < 11; ++it) {
        if (lo < hi) {
            int mid = (lo + hi) >> 1;
            if (__ldg(&idx[mid]) < v) lo = mid + 1; else hi = mid;
        }
    }
    return lo;
}

__global__ void __launch_bounds__(256)
mask_fused_kernel(const float4* __restrict__ inputs,
                  const float4* __restrict__ mask_embedding,
                  const int4*  __restrict__ idx_keep,
                  float* __restrict__ out) {
    // Tiny flag array only — no 4 KB index copy, no LDS binary search.
    __shared__ int s_flag[ROWS_PER_BLOCK];

    const int tid = threadIdx.x;   // 0..255
    const int bid = blockIdx.x;

    if (bid < MAIN_BLOCKS) {
        // ----- main path: 8 consecutive (b,l) rows, one float4 column/thread
        const int row0 = bid * ROWS_PER_BLOCK;
        const int l0   = row0 & (L_DIM - 1);   // 8 rows never straddle a batch

        if (tid < ROWS_PER_BLOCK) s_flag[tid] = 0;

        // Each thread tests its 4 idx values (rank = 4*tid+j) against the
        // window [l0, l0+8). Values are unique -> conflict-free scatter.
        const int4 q = __ldg(&idx_keep[tid]);
        __syncthreads();
        {
            unsigned d;
            d = (unsigned)(q.x - l0); if (d < ROWS_PER_BLOCK) s_flag[d] = 4 * tid + 1;
            d = (unsigned)(q.y - l0); if (d < ROWS_PER_BLOCK) s_flag[d] = 4 * tid + 2;
            d = (unsigned)(q.z - l0); if (d < ROWS_PER_BLOCK) s_flag[d] = 4 * tid + 3;
            d = (unsigned)(q.w - l0); if (d < ROWS_PER_BLOCK) s_flag[d] = 4 * tid + 4;
        }
        __syncthreads();

        float4* __restrict__ dropped = (float4*)(out);               // [B,K,D]
        float4* __restrict__ masked  = (float4*)(out + OFF_MASKED);  // [B,L,D]
        const float4 me = __ldg(&mask_embedding[tid]);

        int flags[ROWS_PER_BLOCK];
        #pragma unroll
        for (int r = 0; r < ROWS_PER_BLOCK; ++r) flags[r] = s_flag[r];

        // front-batch keep-row loads for MLP; streaming (evict-first) reads —
        // input is single-use per iteration.
        float4 v[ROWS_PER_BLOCK];
        #pragma unroll
        for (int r = 0; r < ROWS_PER_BLOCK; ++r) {
            if (flags[r]) {
                v[r] = __ldcs(&inputs[(size_t)(row0 + r) * (D_DIM / 4) + tid]);
            }
        }

        // streaming stores: output lines are dead in L2 after writeback (the
        // next replay overwrites them) — evict-first lets L2 drain them early
        // instead of stalling the next replay's store stream on dirty evictions.
        #pragma unroll
        for (int r = 0; r < ROWS_PER_BLOCK; ++r) {
            const int    row    = row0 + r;
            const size_t row_f4 = (size_t)row * (D_DIM / 4);
            if (flags[r]) {
                const int b = row >> 12;           // row / L_DIM
                const int k = flags[r] - 1;
                __stcs(&masked[row_f4 + tid], v[r]);
                __stcs(&dropped[((size_t)b * NUM_KEEP + k) * (D_DIM / 4) + tid], v[r]);
            } else {
                __stcs(&masked[row_f4 + tid], me);
            }
        }
    } else {
        // ----- tail path: mask_drop (4096 over 16 blocks) + idx echo
        const int* idx32 = (const int*)idx_keep;
        const int tb = bid - MAIN_BLOCKS;          // 0..15
        const int i  = tb * 256 + tid;             // 0..4095
        int pos = lower_bound_g(idx32, i);
        bool kept = (pos < NUM_KEEP && __ldg(&idx32[pos]) == i);
        out[OFF_MASKDROP + i] = kept ? 0.0f : 1.0f;
        if (tb < 4) {
            const int j = tb * 256 + tid;          // 0..1023
            out[OFF_IDX + j] = (float)__ldg(&idx32[j]);
        }
    }
}

// ---------------------------------------------------------------------------
extern "C" void kernel_launch(void* const* d_in, const int* in_sizes, int n_in,
                              void* d_out, int out_size) {
    const float4* inputs         = (const float4*)d_in[0];  // [B, L, D] f32
    const float4* mask_embedding = (const float4*)d_in[1];  // [D] f32
    const int4*   idx_keep       = (const int4*)d_in[2];    // [NUM_KEEP] i32
    float*        out            = (float*)d_out;

    mask_fused_kernel<<<TOTAL_BLOCKS, 256>>>(inputs, mask_embedding, idx_keep, out);
}